// round 17
// baseline (speedup 1.0000x reference)
#include <cuda_runtime.h>
#include <math.h>
#include <stdint.h>

// Problem constants
#define NBT    16384    // B * n_blocks (4 * 4096)
#define CDIM   256      // model channels
#define NB     4096     // blocks (tokens) per batch
#define BATCH  4
#define NLAYERS 4
#define KC320  320      // Eigen TensorContractionBlocking kc cap
#define NPANEL 13       // ceil(4096/320)

#define BK   32         // k-slice per smem stage (320 % 32 == 0)
#define LDA_ 132        // A smem row stride (floats, 528B, 16B-aligned)
#define LDB_ 268        // B smem row stride: normal[0..127]@0, swapped@132
#define SMEM_AB (BK * LDA_ * 4 + BK * LDB_ * 4)   // 16896 + 34304 = 51200 B

typedef unsigned long long u64;

// ---------------- scratch (device globals; no runtime allocation) ----------
__device__ float g_h [NBT * CDIM];
__device__ float g_hp[NBT * CDIM];
__device__ float g_k [NBT * CDIM];
__device__ float g_q [NBT * CDIM];
__device__ float g_v [NBT * CDIM];
__device__ float g_m [(size_t)BATCH * NB * NB];        // 268 MB scores
__device__ float g_pp[(size_t)NPANEL * NBT * CDIM];    // 218 MB av panel partials

// ---------------------------------------------------------------------------
// f32x2 packed helpers: two INDEPENDENT IEEE RN ops per instruction ->
// bitwise identical to scalar fmaf / __fadd_rn on each half.
// ---------------------------------------------------------------------------
__device__ __forceinline__ u64 pack2(float lo, float hi)
{ u64 r; asm("mov.b64 %0, {%1,%2};" : "=l"(r) : "f"(lo), "f"(hi)); return r; }
__device__ __forceinline__ u64 fma2(u64 a, u64 b, u64 c)
{ u64 d; asm("fma.rn.f32x2 %0, %1, %2, %3;" : "=l"(d) : "l"(a), "l"(b), "l"(c)); return d; }
#define UNPACK2(v, lo, hi) \
    asm("mov.b64 {%0,%1}, %2;" : "=f"(lo), "=f"(hi) : "l"(v))

// ---------------------------------------------------------------------------
// XLA:CPU llvm_ir::EmitFastTanh, with_fma=true: clamp +-7.99881172180175781,
// FMA Horner, RN divide, |x|<4e-4 -> x (select on unclamped input).
// ---------------------------------------------------------------------------
__device__ __forceinline__ float tanh_xla(float x)
{
    const float kClamp = 7.99881172180175781f;
    float xc = fminf(fmaxf(x, -kClamp), kClamp);
    float x2 = xc * xc;
    float p = -2.76076847742355e-16f;
    p = fmaf(x2, p,  2.00018790482477e-13f);
    p = fmaf(x2, p, -8.60467152213735e-11f);
    p = fmaf(x2, p,  5.12229709037114e-08f);
    p = fmaf(x2, p,  1.48572235717979e-05f);
    p = fmaf(x2, p,  6.37261928875436e-04f);
    p = fmaf(x2, p,  4.89352455891786e-03f);
    p = xc * p;
    float q = 1.19825839466702e-06f;
    q = fmaf(x2, q, 1.18534705686654e-04f);
    q = fmaf(x2, q, 2.26843463243900e-03f);
    q = fmaf(x2, q, 4.89352518554385e-03f);
    float r = __fdiv_rn(p, q);
    return (fabsf(x) < 0.0004f) ? x : r;
}

// ---------------------------------------------------------------------------
// Anti-diagonal 8x8 microtile: 16 2x2 blocks. Per block:
//   accD = (C[m][n],   C[m+1][n+1])  a2=(a_m,a_m+1)  b2=(b_n,b_n+1)
//   accA = (C[m][n+1], C[m+1][n])    a2 same         b2 swapped copy
// All operands natural u64 from smem -> 6 LDS.128 + 32 FFMA2, NO movs.
// Row pairs pr: base m = (pr<2 ? ty*4+2pr : 64+ty*4+2(pr-2)); cols same w/ tx.
// Each output element keeps its single ascending FMA chain.
// ---------------------------------------------------------------------------
#define MICRO_STEP(AsRow, BsRow)                                          \
    do {                                                                  \
        ulonglong2 alo = *(const ulonglong2*)&(AsRow)[ty << 2];           \
        ulonglong2 ahi = *(const ulonglong2*)&(AsRow)[64 + (ty << 2)];    \
        ulonglong2 bn0 = *(const ulonglong2*)&(BsRow)[tx << 2];           \
        ulonglong2 bn1 = *(const ulonglong2*)&(BsRow)[64 + (tx << 2)];    \
        ulonglong2 bw0 = *(const ulonglong2*)&(BsRow)[132 + (tx << 2)];   \
        ulonglong2 bw1 = *(const ulonglong2*)&(BsRow)[196 + (tx << 2)];   \
        u64 au[4] = {alo.x, alo.y, ahi.x, ahi.y};                         \
        u64 bu[4] = {bn0.x, bn0.y, bn1.x, bn1.y};                         \
        u64 bw[4] = {bw0.x, bw0.y, bw1.x, bw1.y};                         \
        _Pragma("unroll")                                                 \
        for (int pr_ = 0; pr_ < 4; pr_++)                                 \
            _Pragma("unroll")                                             \
            for (int pc_ = 0; pc_ < 4; pc_++) {                           \
                accD[pr_][pc_] = fma2(au[pr_], bu[pc_], accD[pr_][pc_]);  \
                accA[pr_][pc_] = fma2(au[pr_], bw[pc_], accA[pr_][pc_]);  \
            }                                                             \
    } while (0)

#define COMPUTE_STAGE(As, Bs)                                             \
    do {                                                                  \
        _Pragma("unroll")                                                 \
        for (int kk = 0; kk < BK; kk++) MICRO_STEP((As)[kk], (Bs)[kk]);   \
    } while (0)

// Transposing loader, A side (lr = tid>>2 in 0..63, lk = (tid&3)*4).
#define LOAD_NT_A(Sm, Base, LD)                                           \
    do {                                                                  \
        _Pragma("unroll")                                                 \
        for (int rh_ = 0; rh_ < 2; rh_++)                                 \
            _Pragma("unroll")                                             \
            for (int kh_ = 0; kh_ < 2; kh_++) {                           \
                float4 v_ = *(const float4*)((Base) +                     \
                    (size_t)(lr + 64*rh_) * (LD) + k0 + lk + 16*kh_);     \
                int r_ = lr + 64*rh_;                                     \
                (Sm)[lk + 16*kh_ + 0][r_] = v_.x;                         \
                (Sm)[lk + 16*kh_ + 1][r_] = v_.y;                         \
                (Sm)[lk + 16*kh_ + 2][r_] = v_.z;                         \
                (Sm)[lk + 16*kh_ + 3][r_] = v_.w;                         \
            }                                                             \
    } while (0)

// Transposing loader, B side: normal at [n], swapped value-copy at 132+(n^1).
#define LOAD_NT_B(Sm, Base, LD)                                           \
    do {                                                                  \
        _Pragma("unroll")                                                 \
        for (int rh_ = 0; rh_ < 2; rh_++)                                 \
            _Pragma("unroll")                                             \
            for (int kh_ = 0; kh_ < 2; kh_++) {                           \
                float4 v_ = *(const float4*)((Base) +                     \
                    (size_t)(lr + 64*rh_) * (LD) + k0 + lk + 16*kh_);     \
                int r_ = lr + 64*rh_;                                     \
                int rs_ = 132 + (r_ ^ 1);                                 \
                (Sm)[lk + 16*kh_ + 0][r_] = v_.x;                         \
                (Sm)[lk + 16*kh_ + 1][r_] = v_.y;                         \
                (Sm)[lk + 16*kh_ + 2][r_] = v_.z;                         \
                (Sm)[lk + 16*kh_ + 3][r_] = v_.w;                         \
                (Sm)[lk + 16*kh_ + 0][rs_] = v_.x;                        \
                (Sm)[lk + 16*kh_ + 1][rs_] = v_.y;                        \
                (Sm)[lk + 16*kh_ + 2][rs_] = v_.z;                        \
                (Sm)[lk + 16*kh_ + 3][rs_] = v_.w;                        \
            }                                                             \
    } while (0)

// Row/col pair bases for epilogues.
#define ROWP(pr) (((pr) < 2) ? (ty << 2) + 2*(pr) : 64 + (ty << 2) + 2*((pr) - 2))

// Epilogue: write rows m0, m0+1 for all 4 col pairs (dense, no mask).
#define EPILOG_DENSE(Cp, LDN, BN)                                         \
    do {                                                                  \
        _Pragma("unroll")                                                 \
        for (int pr_ = 0; pr_ < 4; pr_++) {                               \
            int m0_ = ROWP(pr_);                                          \
            u64 r0_[4], r1_[4];                                           \
            _Pragma("unroll")                                             \
            for (int pc_ = 0; pc_ < 4; pc_++) {                           \
                float dl_, dh_, al_, ah_;                                 \
                UNPACK2(accD[pr_][pc_], dl_, dh_);                        \
                UNPACK2(accA[pr_][pc_], al_, ah_);                        \
                r0_[pc_] = pack2(dl_, al_);                               \
                r1_[pc_] = pack2(ah_, dh_);                               \
            }                                                             \
            ulonglong2 w0_ = {r0_[0], r0_[1]}, w1_ = {r0_[2], r0_[3]};    \
            ulonglong2 w2_ = {r1_[0], r1_[1]}, w3_ = {r1_[2], r1_[3]};    \
            *(ulonglong2*)((Cp) + (size_t)m0_ * (LDN) + (BN) + (tx << 2))      = w0_; \
            *(ulonglong2*)((Cp) + (size_t)m0_ * (LDN) + (BN) + 64 + (tx << 2)) = w1_; \
            *(ulonglong2*)((Cp) + (size_t)(m0_+1) * (LDN) + (BN) + (tx << 2))      = w2_; \
            *(ulonglong2*)((Cp) + (size_t)(m0_+1) * (LDN) + (BN) + 64 + (tx << 2)) = w3_; \
        }                                                                 \
    } while (0)

// ---------------------------------------------------------------------------
// gemm_nt: C[m,n] = sum_k A[m,k] * B[n,k]   (A: MxK, B: NxK, row-major)
// ---------------------------------------------------------------------------
__global__ void __launch_bounds__(256, 2)
gemm_nt(const float* __restrict__ A, const float* __restrict__ B,
        float* __restrict__ C, int M, int N, int K)
{
    extern __shared__ char dyn[];
    float (*As)[LDA_] = (float(*)[LDA_])dyn;
    float (*Bs)[LDB_] = (float(*)[LDB_])(dyn + BK * LDA_ * 4);

    const int bm = blockIdx.y << 7;
    const int bn = blockIdx.x << 7;
    const int tid = threadIdx.x;
    const int tx = tid & 15, ty = tid >> 4;
    const int lr = tid >> 2;
    const int lk = (tid & 3) << 2;

    u64 accD[4][4], accA[4][4];
    #pragma unroll
    for (int i = 0; i < 4; i++)
        #pragma unroll
        for (int j = 0; j < 4; j++) { accD[i][j] = 0ull; accA[i][j] = 0ull; }

    for (int k0 = 0; k0 < K; k0 += BK) {
        LOAD_NT_A(As, A + (size_t)bm * K, K);
        LOAD_NT_B(Bs, B + (size_t)bn * K, K);
        __syncthreads();
        COMPUTE_STAGE(As, Bs);
        __syncthreads();
    }

    float* Cb = C + bm * (size_t)N;   // rows offset by bm
    EPILOG_DENSE(Cb, N, bn);
}

// ---------------------------------------------------------------------------
// gemm_nt_kqv: three NT GEMMs sharing input A (hp): z picks {Wk,Wq,Wv}.
// ---------------------------------------------------------------------------
__global__ void __launch_bounds__(256, 2)
gemm_nt_kqv(const float* __restrict__ A,
            const float* __restrict__ W0, const float* __restrict__ W1,
            const float* __restrict__ W2,
            float* __restrict__ C0, float* __restrict__ C1,
            float* __restrict__ C2)
{
    const float* B = (blockIdx.z == 0) ? W0 : (blockIdx.z == 1) ? W1 : W2;
    float*       C = (blockIdx.z == 0) ? C0 : (blockIdx.z == 1) ? C1 : C2;

    extern __shared__ char dyn[];
    float (*As)[LDA_] = (float(*)[LDA_])dyn;
    float (*Bs)[LDB_] = (float(*)[LDB_])(dyn + BK * LDA_ * 4);

    const int bm = blockIdx.y << 7;
    const int bn = blockIdx.x << 7;
    const int tid = threadIdx.x;
    const int tx = tid & 15, ty = tid >> 4;
    const int lr = tid >> 2;
    const int lk = (tid & 3) << 2;

    u64 accD[4][4], accA[4][4];
    #pragma unroll
    for (int i = 0; i < 4; i++)
        #pragma unroll
        for (int j = 0; j < 4; j++) { accD[i][j] = 0ull; accA[i][j] = 0ull; }

    for (int k0 = 0; k0 < CDIM; k0 += BK) {
        LOAD_NT_A(As, A + (size_t)bm * CDIM, CDIM);
        LOAD_NT_B(Bs, B + (size_t)bn * CDIM, CDIM);
        __syncthreads();
        COMPUTE_STAGE(As, Bs);
        __syncthreads();
    }

    float* Cb = C + bm * (size_t)CDIM;
    EPILOG_DENSE(Cb, CDIM, bn);
}

// ---------------------------------------------------------------------------
// scores: per batch b, M[t,s] = sum_c K[t,c] * Q[s,c], masked (t<s -> 0).
// ---------------------------------------------------------------------------
__global__ void __launch_bounds__(256, 2)
scores_kernel(const float* __restrict__ Kin, const float* __restrict__ Qin,
              float* __restrict__ Mout)
{
    const int bt = blockIdx.y << 7;   // t tile (output rows)
    const int bs = blockIdx.x << 7;   // s tile (output cols)
    if (bt + 127 < bs) return;        // fully upper triangle: unused

    extern __shared__ char dyn[];
    float (*As)[LDA_] = (float(*)[LDA_])dyn;
    float (*Bs)[LDB_] = (float(*)[LDB_])(dyn + BK * LDA_ * 4);

    const int b = blockIdx.z;
    const float* Kb = Kin + (size_t)b * NB * CDIM;
    const float* Qb = Qin + (size_t)b * NB * CDIM;
    float*       Mb = Mout + (size_t)b * NB * NB;

    const int tid = threadIdx.x;
    const int tx = tid & 15, ty = tid >> 4;
    const int lr = tid >> 2;
    const int lk = (tid & 3) << 2;

    u64 accD[4][4], accA[4][4];
    #pragma unroll
    for (int i = 0; i < 4; i++)
        #pragma unroll
        for (int j = 0; j < 4; j++) { accD[i][j] = 0ull; accA[i][j] = 0ull; }

    for (int k0 = 0; k0 < CDIM; k0 += BK) {
        LOAD_NT_A(As, Kb + (size_t)bt * CDIM, CDIM);
        LOAD_NT_B(Bs, Qb + (size_t)bs * CDIM, CDIM);
        __syncthreads();
        COMPUTE_STAGE(As, Bs);
        __syncthreads();
    }

    if (bt >= bs + 127) {             // interior: whole tile below diagonal
        float* Cb = Mb + (size_t)bt * NB;
        EPILOG_DENSE(Cb, NB, bs);
    } else {                           // diagonal tile: per-element mask
        #pragma unroll
        for (int pr = 0; pr < 4; pr++) {
            int t0 = bt + ROWP(pr);
            #pragma unroll
            for (int pc = 0; pc < 4; pc++) {
                int s0 = bs + ((pc < 2) ? (tx << 2) + 2*pc
                                        : 64 + (tx << 2) + 2*(pc - 2));
                float dl, dh, al, ah;
                UNPACK2(accD[pr][pc], dl, dh);
                UNPACK2(accA[pr][pc], al, ah);
                Mb[(size_t)t0 * NB + s0]           = (t0 < s0)     ? 0.f : dl;
                Mb[(size_t)t0 * NB + s0 + 1]       = (t0 < s0 + 1) ? 0.f : al;
                Mb[(size_t)(t0+1) * NB + s0]       = (t0+1 < s0)   ? 0.f : ah;
                Mb[(size_t)(t0+1) * NB + s0 + 1]   = (t0+1 < s0+1) ? 0.f : dh;
            }
        }
    }
}

// ---------------------------------------------------------------------------
// av_panel: partial[j][sg][c] = sum over t in panel j (ascending FMA chain)
// of M[t,s] * V[t,c]. M (A side) copied straight (s consecutive); V (B side)
// stored normal + pair-swapped. t starts at max(panel_lo, bs): skipped prefix
// is exact zeros (fma no-ops).
// ---------------------------------------------------------------------------
__global__ void __launch_bounds__(256, 2)
av_panel_kernel(const float* __restrict__ Min, const float* __restrict__ Vin,
                float* __restrict__ Pp)
{
    const int jp = blockIdx.x >> 1;          // panel 0..12
    const int cc = blockIdx.x & 1;           // c half
    const int bs = blockIdx.y << 7;          // s tile base (batch-local)
    const int b  = blockIdx.z;

    const int t_lo0 = jp * KC320;
    const int t_hi  = min(t_lo0 + KC320, NB);
    const int t_lo  = max(t_lo0, bs);
    if (t_lo >= t_hi) return;                // panel entirely masked: all-zero

    extern __shared__ char dyn[];
    float (*Ms)[LDA_] = (float(*)[LDA_])dyn;                 // M[t][s-local]
    float (*Vs)[LDB_] = (float(*)[LDB_])(dyn + BK * LDA_ * 4);

    const int bc = cc << 7;
    const float* Mb = Min + (size_t)b * NB * NB;
    const float* Vb = Vin + (size_t)b * NB * CDIM;

    const int tid = threadIdx.x;
    const int tx = tid & 15, ty = tid >> 4;
    const int mr = tid >> 3;          // 0..31 (t-local row)
    const int mc = (tid & 7) << 2;    // 0,4,...,28

    u64 accD[4][4], accA[4][4];
    #pragma unroll
    for (int i = 0; i < 4; i++)
        #pragma unroll
        for (int j = 0; j < 4; j++) { accD[i][j] = 0ull; accA[i][j] = 0ull; }

    for (int t0 = t_lo; t0 < t_hi; t0 += BK) {
        const float* Mrow = Mb + (size_t)(t0 + mr) * NB + bs;
        const float* Vrow = Vb + (size_t)(t0 + mr) * CDIM + bc;
        #pragma unroll
        for (int jj = 0; jj < 4; jj++) {
            float4 mv = *(const float4*)(Mrow + mc + 32*jj);
            float4 vv = *(const float4*)(Vrow + mc + 32*jj);
            *(float4*)&Ms[mr][mc + 32*jj] = mv;
            *(float4*)&Vs[mr][mc + 32*jj] = vv;
            float4 vs = {vv.y, vv.x, vv.w, vv.z};       // pair-swapped copy
            *(float4*)&Vs[mr][132 + mc + 32*jj] = vs;
        }
        __syncthreads();
        COMPUTE_STAGE(Ms, Vs);
        __syncthreads();
    }

    float* Pj = Pp + (size_t)jp * NBT * CDIM + (size_t)b * NB * CDIM
              + (size_t)bs * CDIM;
    EPILOG_DENSE(Pj, CDIM, bc);
}

// ---------------------------------------------------------------------------
// av_combine: H[sg,c] = tanh( sum_{j ascending} partial[j][sg][c] ), RN adds
// starting from 0 -- identical sequence to the R11 flush chain (rel_err 0.0).
// jmin = bs/320 skips panels that are exact zero for the whole s-tile.
// ---------------------------------------------------------------------------
__global__ void __launch_bounds__(256)
av_combine_kernel(const float* __restrict__ Pp, float* __restrict__ Hout)
{
    const int gid = blockIdx.x * 256 + threadIdx.x;    // one float4 each
    const int sg  = gid >> 6;                          // row (0..NBT-1)
    const int c4  = (gid & 63) << 2;
    const int bs  = (sg & (NB - 1)) & ~127;            // s-tile base in batch
    const int jmin = bs / KC320;

    float4 tot = {0.f, 0.f, 0.f, 0.f};
    for (int j = jmin; j < NPANEL; j++) {
        float4 p = *(const float4*)(Pp + ((size_t)j * NBT + sg) * CDIM + c4);
        tot.x = __fadd_rn(tot.x, p.x);
        tot.y = __fadd_rn(tot.y, p.y);
        tot.z = __fadd_rn(tot.z, p.z);
        tot.w = __fadd_rn(tot.w, p.w);
    }
    float4 o;
    o.x = tanh_xla(tot.x); o.y = tanh_xla(tot.y);
    o.z = tanh_xla(tot.z); o.w = tanh_xla(tot.w);
    *(float4*)(Hout + (size_t)sg * CDIM + c4) = o;
}

// ---------------------------------------------------------------------------
extern "C" void kernel_launch(void* const* d_in, const int* in_sizes, int n_in,
                              void* d_out, int out_size)
{
    const float* x     = (const float*)d_in[0];   // (4,1,524288)
    const float* W_in  = (const float*)d_in[1];   // (256,128)
    const float* Wp    = (const float*)d_in[2];   // (4,256,256)
    const float* Wk    = (const float*)d_in[3];
    const float* Wv    = (const float*)d_in[4];
    const float* Wq    = (const float*)d_in[5];
    const float* W_out = (const float*)d_in[6];   // (128,256)
    float* out = (float*)d_out;                   // (4,4096,128)

    float *h, *hp, *kb, *qb, *vb, *mm, *pp;
    cudaGetSymbolAddress((void**)&h,  g_h);
    cudaGetSymbolAddress((void**)&hp, g_hp);
    cudaGetSymbolAddress((void**)&kb, g_k);
    cudaGetSymbolAddress((void**)&qb, g_q);
    cudaGetSymbolAddress((void**)&vb, g_v);
    cudaGetSymbolAddress((void**)&mm, g_m);
    cudaGetSymbolAddress((void**)&pp, g_pp);

    static int attr_done = 0;
    if (!attr_done) {
        cudaFuncSetAttribute(gemm_nt,
            cudaFuncAttributeMaxDynamicSharedMemorySize, SMEM_AB);
        cudaFuncSetAttribute(gemm_nt_kqv,
            cudaFuncAttributeMaxDynamicSharedMemorySize, SMEM_AB);
        cudaFuncSetAttribute(scores_kernel,
            cudaFuncAttributeMaxDynamicSharedMemorySize, SMEM_AB);
        cudaFuncSetAttribute(av_panel_kernel,
            cudaFuncAttributeMaxDynamicSharedMemorySize, SMEM_AB);
        attr_done = 1;
    }

    const dim3 blk(256);

    // Input projection: h = blocked_x @ W_in^T   (16384 x 256, K=128)
    gemm_nt<<<dim3(CDIM/128, NBT/128), blk, SMEM_AB>>>(x, W_in, h, NBT, CDIM, 128);

    for (int l = 0; l < NLAYERS; l++) {
        const float* wp = Wp + (size_t)l * CDIM * CDIM;
        const float* wk = Wk + (size_t)l * CDIM * CDIM;
        const float* wv = Wv + (size_t)l * CDIM * CDIM;
        const float* wq = Wq + (size_t)l * CDIM * CDIM;

        // hp = h @ wp^T, then K/Q/V = hp @ {wk,wq,wv}^T batched over z
        gemm_nt<<<dim3(2, NBT/128), blk, SMEM_AB>>>(h, wp, hp, NBT, CDIM, CDIM);
        gemm_nt_kqv<<<dim3(2, NBT/128, 3), blk, SMEM_AB>>>(hp, wk, wq, wv, kb, qb, vb);

        // M[t,s] = k_t . q_s, tril (per batch), K=256: single panel
        scores_kernel<<<dim3(NB/128, NB/128, BATCH), blk, SMEM_AB>>>(kb, qb, mm);

        // av panel partials (balanced grid), then ordered combine + tanh
        av_panel_kernel<<<dim3(2*NPANEL, NB/128, BATCH), blk, SMEM_AB>>>(mm, vb, pp);
        av_combine_kernel<<<dim3(NBT*CDIM/4/256), blk>>>(pp, h);
    }

    // Output projection: out = h @ W_out^T   (16384 x 128, K=256)
    gemm_nt<<<dim3(1, NBT/128), blk, SMEM_AB>>>(h, W_out, out, NBT, 128, CDIM);
}